// round 1
// baseline (speedup 1.0000x reference)
#include <cuda_runtime.h>
#include <math.h>

#define NMAX 50000
#define EMAX 1600000
#define D 128
#define T 8

// ---- scratch (static device globals; no allocation anywhere) ----
__device__ float g_bufA[NMAX * D];
__device__ float g_bufB[NMAX * D];
__device__ int   g_deg[NMAX];
__device__ int   g_rowstart[NMAX + 1];
__device__ int   g_cursor[NMAX];
__device__ int   g_csr[EMAX];
__device__ float g_invdeg[NMAX];
__device__ float g_colsum[2 * D];

// ---------------- CSR build ----------------
__global__ void k_zero_deg(int n) {
    int i = blockIdx.x * blockDim.x + threadIdx.x;
    if (i < n) g_deg[i] = 0;
}

__global__ void k_count(const int* __restrict__ dst, int e) {
    int i = blockIdx.x * blockDim.x + threadIdx.x;
    if (i < e) atomicAdd(&g_deg[dst[i]], 1);
}

// single-block exclusive scan over degrees; also writes cursor + inv_deg
__global__ void k_scan(int n) {
    __shared__ int sd[1024];
    int tid = threadIdx.x;
    int offset = 0;
    for (int base = 0; base < n; base += 1024) {
        int i = base + tid;
        int v = (i < n) ? g_deg[i] : 0;
        sd[tid] = v;
        __syncthreads();
        for (int s = 1; s < 1024; s <<= 1) {
            int add = (tid >= s) ? sd[tid - s] : 0;
            __syncthreads();
            sd[tid] += add;
            __syncthreads();
        }
        int excl = sd[tid] - v + offset;   // exclusive prefix
        if (i < n) {
            g_rowstart[i] = excl;
            g_cursor[i]   = excl;
            g_invdeg[i]   = 1.0f / fmaxf((float)v, 1.0f);
        }
        offset += sd[1023];
        __syncthreads();
    }
    if (tid == 0) g_rowstart[n] = offset;
}

__global__ void k_fill(const int* __restrict__ src, const int* __restrict__ dst, int e) {
    int i = blockIdx.x * blockDim.x + threadIdx.x;
    if (i < e) {
        int p = atomicAdd(&g_cursor[dst[i]], 1);
        g_csr[p] = src[i];
    }
}

// ---------------- fused aggregate (mean over in-edges) + GEMM + bias ----------------
// block = 128 threads (one per feature), handles T=8 nodes.
// sel_in: -1 = external feat pointer, 0 = g_bufA, 1 = g_bufB. sel_out: 0/1.
__global__ void __launch_bounds__(128) k_layer(
    const float* __restrict__ feat, int sel_in, int sel_out,
    const float* __restrict__ W, const float* __restrict__ bias, int n)
{
    const float* __restrict__ h_in  = (sel_in < 0) ? feat : (sel_in == 0 ? g_bufA : g_bufB);
    float* __restrict__       h_out = (sel_out == 0) ? g_bufA : g_bufB;

    __shared__ float rows[D][T];   // [k][t], t contiguous for LDS.128 in GEMM phase
    int tid  = threadIdx.x;
    int base = blockIdx.x * T;

    // aggregation: thread tid accumulates feature column tid for each of T nodes
    #pragma unroll
    for (int t = 0; t < T; t++) {
        int node = base + t;
        float acc = 0.f;
        if (node < n) {
            int s = g_rowstart[node];
            int e = g_rowstart[node + 1];
            float a0 = 0.f, a1 = 0.f, a2 = 0.f, a3 = 0.f;
            int i = s;
            for (; i + 4 <= e; i += 4) {
                int c0 = g_csr[i], c1 = g_csr[i + 1], c2 = g_csr[i + 2], c3 = g_csr[i + 3];
                a0 += h_in[(size_t)c0 * D + tid];
                a1 += h_in[(size_t)c1 * D + tid];
                a2 += h_in[(size_t)c2 * D + tid];
                a3 += h_in[(size_t)c3 * D + tid];
            }
            for (; i < e; i++) a0 += h_in[(size_t)g_csr[i] * D + tid];
            acc = ((a0 + a1) + (a2 + a3)) * g_invdeg[node];
        }
        rows[tid][t] = acc;
    }
    __syncthreads();

    // GEMM: out[node][tid] = sum_k rows[k][node] * W[k][tid] + b[tid]
    float acc8[T];
    float bv = bias[tid];
    #pragma unroll
    for (int t = 0; t < T; t++) acc8[t] = bv;

    #pragma unroll 4
    for (int k = 0; k < D; k++) {
        float w = W[k * D + tid];
        float4 r0 = *(const float4*)&rows[k][0];
        float4 r1 = *(const float4*)&rows[k][4];
        acc8[0] += r0.x * w; acc8[1] += r0.y * w;
        acc8[2] += r0.z * w; acc8[3] += r0.w * w;
        acc8[4] += r1.x * w; acc8[5] += r1.y * w;
        acc8[6] += r1.z * w; acc8[7] += r1.w * w;
    }

    #pragma unroll
    for (int t = 0; t < T; t++) {
        int node = base + t;
        if (node < n) h_out[(size_t)node * D + tid] = acc8[t];
    }
}

// ---------------- readout: column sums over final h (in g_bufA) ----------------
__global__ void k_zero_col() { g_colsum[threadIdx.x] = 0.f; }  // <<<1, 256>>>

__global__ void k_colsum(int n, int gsel) {
    float acc = 0.f;
    for (int node = blockIdx.x; node < n; node += gridDim.x)
        acc += g_bufA[(size_t)node * D + threadIdx.x];
    atomicAdd(&g_colsum[gsel * D + threadIdx.x], acc);
}

// ---------------- final: readout MLP + match MLP + sigmoid ----------------
__global__ void k_match(const float* __restrict__ Wr,  const float* __restrict__ br,
                        const float* __restrict__ Wm1, const float* __restrict__ bm1,
                        const float* __restrict__ Wm2, const float* __restrict__ bm2,
                        float n_nodes, float* __restrict__ out)
{
    __shared__ float c[2 * D];
    __shared__ float red[D];
    int tid = threadIdx.x;          // 256 threads
    int g = tid / D;
    int j = tid % D;
    float invn = 1.0f / n_nodes;

    float acc = br[j];
    for (int k = 0; k < D; k++)
        acc += (g_colsum[g * D + k] * invn) * Wr[k * D + j];
    c[tid] = 1.0f / (1.0f + expf(-acc));    // g_p / g_s, concatenated
    __syncthreads();

    if (tid < D) {
        float d1 = bm1[tid];
        for (int i = 0; i < 2 * D; i++)
            d1 += c[i] * Wm1[i * D + tid];
        red[tid] = d1 * Wm2[tid];
    }
    __syncthreads();

    if (tid == 0) {
        float s = 0.f;
        for (int i = 0; i < D; i++) s += red[i];
        float d = s + bm2[0];
        out[0] = 1.0f / (1.0f + expf(-d));
    }
}

// ---------------- launch ----------------
extern "C" void kernel_launch(void* const* d_in, const int* in_sizes, int n_in,
                              void* d_out, int out_size)
{
    const float* feat[2] = { (const float*)d_in[0], (const float*)d_in[3] };
    const int*   src[2]  = { (const int*)d_in[1],   (const int*)d_in[4]   };
    const int*   dst[2]  = { (const int*)d_in[2],   (const int*)d_in[5]   };
    const float* W[3]    = { (const float*)d_in[6], (const float*)d_in[8], (const float*)d_in[10] };
    const float* b[3]    = { (const float*)d_in[7], (const float*)d_in[9], (const float*)d_in[11] };
    const float* Wr  = (const float*)d_in[12];
    const float* br  = (const float*)d_in[13];
    const float* Wm1 = (const float*)d_in[14];
    const float* bm1 = (const float*)d_in[15];
    const float* Wm2 = (const float*)d_in[16];
    const float* bm2 = (const float*)d_in[17];

    int n = in_sizes[0] / D;

    k_zero_col<<<1, 256>>>();

    for (int gi = 0; gi < 2; gi++) {
        int e = in_sizes[1 + 3 * gi];
        k_zero_deg<<<(n + 511) / 512, 512>>>(n);
        k_count<<<(e + 511) / 512, 512>>>(dst[gi], e);
        k_scan<<<1, 1024>>>(n);
        k_fill<<<(e + 511) / 512, 512>>>(src[gi], dst[gi], e);

        int nb = (n + T - 1) / T;
        k_layer<<<nb, 128>>>(feat[gi], -1, 0, W[0], b[0], n);  // feat -> A
        k_layer<<<nb, 128>>>(feat[gi],  0, 1, W[1], b[1], n);  // A -> B
        k_layer<<<nb, 128>>>(feat[gi],  1, 0, W[2], b[2], n);  // B -> A

        k_colsum<<<512, 128>>>(n, gi);
    }

    k_match<<<1, 256>>>(Wr, br, Wm1, bm1, Wm2, bm2, (float)n, (float*)d_out);
}